// round 4
// baseline (speedup 1.0000x reference)
#include <cuda_runtime.h>
#include <cuda_bf16.h>
#include <float.h>

// VectorQuantizer: N=131072 tokens (32 x 64 x 64 NCHW), D=64, K=512.
// Outputs packed fp32: [indices 131072][quantized_st NCHW 8388608][loss 1].
//
// Bit-replicates the reference numerics so argmin decisions match:
//   xsq   = sequential Sum round(x_d^2)          (rounded products, no FMA)
//   dot_k = sequential FMA over d, acc init 0    (Eigen/BLAS microkernel order)
//   dist  = fadd(fadd(xsq, -2*dot), wsq_k)       (left-to-right, x2 exact)
//   argmin: strict <, ascending k (first-occurrence ties)
//   quantized_st = fadd(x, fsub(q, x))
//   loss = 1.25 * mean((q - x)^2)

#define NTOK    131072
#define DIM     64
#define KCODES  512
#define HW      4096
#define THREADS 512
#define BLOCKS  (NTOK / THREADS)  // 256

__device__ float g_part[BLOCKS];

__device__ __forceinline__ unsigned long long fma2(unsigned long long a,
                                                   unsigned long long b,
                                                   unsigned long long c) {
    unsigned long long d;
    asm("fma.rn.f32x2 %0, %1, %2, %3;" : "=l"(d) : "l"(a), "l"(b), "l"(c));
    return d;
}

__global__ __launch_bounds__(THREADS, 1) void vq_main(
    const float* __restrict__ in,   // [32, 64, 64, 64] NCHW
    const float* __restrict__ w,    // [512, 64]
    float* __restrict__ out_idx,    // [131072]
    float* __restrict__ out_q)      // [32, 64, 64, 64] NCHW
{
    extern __shared__ float sm[];
    float* wt  = sm;                 // [64][512] transposed weight
    float* wsq = sm + DIM * KCODES;  // [512] ||w_k||^2
    float* red = wsq + KCODES;       // [16] reduction scratch

    for (int e = threadIdx.x; e < KCODES * DIM; e += THREADS) {
        int k = e >> 6, d = e & 63;
        wt[d * KCODES + k] = w[e];
    }
    __syncthreads();

    // ||w_k||^2: sequential, separately-rounded products (matches XLA reduce)
    {
        int k = threadIdx.x;
        if (k < KCODES) {
            float s = 0.f;
            for (int d = 0; d < DIM; d++) {
                float v = wt[d * KCODES + k];
                s = __fadd_rn(s, __fmul_rn(v, v));
            }
            wsq[k] = s;
        }
    }
    __syncthreads();

    int t = blockIdx.x * THREADS + threadIdx.x;  // token = b*4096 + h*64 + w
    const float* px = in + ((t >> 12) * (DIM * HW)) + (t & (HW - 1));

    float xv[DIM];
    #pragma unroll
    for (int d = 0; d < DIM; d++) xv[d] = px[d * HW];

    // ||x||^2: sequential scalar, rounded mul then rounded add (NO fma)
    float xsq = 0.f;
    #pragma unroll
    for (int d = 0; d < DIM; d++)
        xsq = __fadd_rn(xsq, __fmul_rn(xv[d], xv[d]));

    float best = FLT_MAX;
    int bestk = 0;

    for (int kb = 0; kb < KCODES; kb += 16) {
        // 8 packed accumulators = 16 dots, init 0 (reference matmul starts at 0)
        unsigned long long acc[8];
        #pragma unroll
        for (int j = 0; j < 8; j++) acc[j] = 0ull;

        #pragma unroll
        for (int d = 0; d < DIM; d++) {
            unsigned long long x2;
            asm("mov.b64 %0, {%1, %1};" : "=l"(x2) : "f"(xv[d]));
            const ulonglong2* row =
                reinterpret_cast<const ulonglong2*>(wt + d * KCODES + kb);
            #pragma unroll
            for (int q = 0; q < 4; q++) {
                ulonglong2 wp = row[q];           // LDS.128
                acc[2 * q]     = fma2(x2, wp.x, acc[2 * q]);
                acc[2 * q + 1] = fma2(x2, wp.y, acc[2 * q + 1]);
            }
        }

        #pragma unroll
        for (int j = 0; j < 8; j++) {
            float s0 = __uint_as_float((unsigned)(acc[j] & 0xffffffffull));
            float s1 = __uint_as_float((unsigned)(acc[j] >> 32));
            // dist = (xsq - 2*dot) + wsq   (each op rounded once; *2 exact)
            float d0 = __fadd_rn(__fadd_rn(xsq, -2.0f * s0), wsq[kb + 2 * j]);
            float d1 = __fadd_rn(__fadd_rn(xsq, -2.0f * s1), wsq[kb + 2 * j + 1]);
            if (d0 < best) { best = d0; bestk = kb + 2 * j; }
            if (d1 < best) { best = d1; bestk = kb + 2 * j + 1; }
        }
    }

    // Epilogue: straight-through output and loss partial.
    float part = 0.f;
    float* pq = out_q + ((t >> 12) * (DIM * HW)) + (t & (HW - 1));
    #pragma unroll
    for (int d = 0; d < DIM; d++) {
        float qv = wt[d * KCODES + bestk];
        float e  = __fsub_rn(qv, xv[d]);          // q - x (one rounding)
        pq[d * HW] = __fadd_rn(xv[d], e);         // x + (q - x)
        part = fmaf(e, e, part);
    }
    out_idx[t] = (float)bestk;

    #pragma unroll
    for (int o = 16; o > 0; o >>= 1)
        part += __shfl_xor_sync(0xffffffffu, part, o);
    int wid = threadIdx.x >> 5, lid = threadIdx.x & 31;
    if (lid == 0) red[wid] = part;
    __syncthreads();
    if (wid == 0) {
        float v = (lid < THREADS / 32) ? red[lid] : 0.f;
        #pragma unroll
        for (int o = 8; o > 0; o >>= 1)
            v += __shfl_xor_sync(0xffffffffu, v, o);
        if (lid == 0) g_part[blockIdx.x] = v;
    }
}

__global__ void vq_finalize(float* __restrict__ out_loss) {
    __shared__ double s[BLOCKS];
    s[threadIdx.x] = (double)g_part[threadIdx.x];
    __syncthreads();
    for (int o = BLOCKS / 2; o > 0; o >>= 1) {
        if (threadIdx.x < o) s[threadIdx.x] += s[threadIdx.x + o];
        __syncthreads();
    }
    if (threadIdx.x == 0)
        out_loss[0] = (float)(s[0] * (1.25 / 8388608.0));
}

extern "C" void kernel_launch(void* const* d_in, const int* in_sizes, int n_in,
                              void* d_out, int out_size) {
    const float* in = (const float*)d_in[0];
    const float* w  = (const float*)d_in[1];
    float* out      = (float*)d_out;

    float* out_idx  = out;
    float* out_q    = out + NTOK;
    float* out_loss = out + NTOK + NTOK * DIM;

    int smem = (DIM * KCODES + KCODES + 16) * (int)sizeof(float);
    cudaFuncSetAttribute(vq_main, cudaFuncAttributeMaxDynamicSharedMemorySize, smem);
    vq_main<<<BLOCKS, THREADS, smem>>>(in, w, out_idx, out_q);
    vq_finalize<<<1, BLOCKS>>>(out_loss);
}

// round 5
// speedup vs baseline: 1.1804x; 1.1804x over previous
#include <cuda_runtime.h>
#include <cuda_bf16.h>
#include <float.h>

// VectorQuantizer: N=131072 tokens (32 x 64 x 64 NCHW), D=64, K=512.
// Outputs packed fp32: [indices 131072][quantized_st NCHW 8388608][loss 1].
//
// Bit-replicates reference numerics (proven rel_err 0.0 in R3):
//   xsq   sequential rounded-mul/rounded-add; dot sequential FMA acc=0;
//   dist = fadd(fadd(xsq, -2*dot), wsq); strict-< ascending-k argmin;
//   quantized_st = fadd(x, fsub(q, x)); loss = 1.25*mean((q-x)^2).
//
// R4: persistent 148-CTA kernel, 128 threads (1 warp/SMSP) so the FMA pipe,
// not the issue port, is the binding resource. Tile = 128 tokens, 1024 tiles
// round-robin -> 1.01x load balance (max 896 tokens/SM vs 886 floor).

#define NTOK    131072
#define DIM     64
#define KCODES  512
#define HW      4096
#define THREADS 128
#define GRID    148
#define NTILES  (NTOK / THREADS)   // 1024

__device__ float g_part[GRID];

__device__ __forceinline__ unsigned long long fma2(unsigned long long a,
                                                   unsigned long long b,
                                                   unsigned long long c) {
    unsigned long long d;
    asm("fma.rn.f32x2 %0, %1, %2, %3;" : "=l"(d) : "l"(a), "l"(b), "l"(c));
    return d;
}

__global__ __launch_bounds__(THREADS, 1) void vq_main(
    const float* __restrict__ in,   // [32, 64, 64, 64] NCHW
    const float* __restrict__ w,    // [512, 64]
    float* __restrict__ out_idx,    // [131072]
    float* __restrict__ out_q)      // [32, 64, 64, 64] NCHW
{
    extern __shared__ float sm[];
    float* wt  = sm;                 // [64][512] transposed weight
    float* wsq = sm + DIM * KCODES;  // [512]
    float* red = wsq + KCODES;       // [4]

    for (int e = threadIdx.x; e < KCODES * DIM; e += THREADS) {
        int k = e >> 6, d = e & 63;
        wt[d * KCODES + k] = w[e];
    }
    __syncthreads();

    // ||w_k||^2: sequential rounded products (4 codes per thread)
    for (int k = threadIdx.x; k < KCODES; k += THREADS) {
        float s = 0.f;
        for (int d = 0; d < DIM; d++) {
            float v = wt[d * KCODES + k];
            s = __fadd_rn(s, __fmul_rn(v, v));
        }
        wsq[k] = s;
    }
    __syncthreads();

    float loss_acc = 0.f;

    for (int tile = blockIdx.x; tile < NTILES; tile += GRID) {
        int t = tile * THREADS + threadIdx.x;      // token = b*4096 + h*64 + w
        const float* px = in + ((t >> 12) * (DIM * HW)) + (t & (HW - 1));

        float xv[DIM];
        #pragma unroll
        for (int d = 0; d < DIM; d++) xv[d] = px[d * HW];

        // ||x||^2: sequential scalar, rounded mul then rounded add (NO fma)
        float xsq = 0.f;
        #pragma unroll
        for (int d = 0; d < DIM; d++)
            xsq = __fadd_rn(xsq, __fmul_rn(xv[d], xv[d]));

        float best = FLT_MAX;
        int bestk = 0;

        for (int kb = 0; kb < KCODES; kb += 16) {
            unsigned long long acc[8];
            #pragma unroll
            for (int j = 0; j < 8; j++) acc[j] = 0ull;

            #pragma unroll
            for (int d = 0; d < DIM; d++) {
                unsigned long long x2;
                asm("mov.b64 %0, {%1, %1};" : "=l"(x2) : "f"(xv[d]));
                const ulonglong2* row =
                    reinterpret_cast<const ulonglong2*>(wt + d * KCODES + kb);
                #pragma unroll
                for (int q = 0; q < 4; q++) {
                    ulonglong2 wp = row[q];        // LDS.128 broadcast
                    acc[2 * q]     = fma2(x2, wp.x, acc[2 * q]);
                    acc[2 * q + 1] = fma2(x2, wp.y, acc[2 * q + 1]);
                }
            }

            #pragma unroll
            for (int j = 0; j < 8; j++) {
                float s0 = __uint_as_float((unsigned)(acc[j] & 0xffffffffull));
                float s1 = __uint_as_float((unsigned)(acc[j] >> 32));
                float d0 = __fadd_rn(__fadd_rn(xsq, -2.0f * s0), wsq[kb + 2 * j]);
                float d1 = __fadd_rn(__fadd_rn(xsq, -2.0f * s1), wsq[kb + 2 * j + 1]);
                if (d0 < best) { best = d0; bestk = kb + 2 * j; }
                if (d1 < best) { best = d1; bestk = kb + 2 * j + 1; }
            }
        }

        // Epilogue: straight-through output and loss partial.
        float* pq = out_q + ((t >> 12) * (DIM * HW)) + (t & (HW - 1));
        #pragma unroll
        for (int d = 0; d < DIM; d++) {
            float qv = wt[d * KCODES + bestk];
            float e  = __fsub_rn(qv, xv[d]);       // q - x (one rounding)
            pq[d * HW] = __fadd_rn(xv[d], e);      // x + (q - x)
            loss_acc = fmaf(e, e, loss_acc);
        }
        out_idx[t] = (float)bestk;
    }

    // Deterministic per-CTA loss reduction
    #pragma unroll
    for (int o = 16; o > 0; o >>= 1)
        loss_acc += __shfl_xor_sync(0xffffffffu, loss_acc, o);
    int wid = threadIdx.x >> 5, lid = threadIdx.x & 31;
    if (lid == 0) red[wid] = loss_acc;
    __syncthreads();
    if (threadIdx.x == 0) {
        double s = 0.0;
        for (int i = 0; i < THREADS / 32; i++) s += (double)red[i];
        g_part[blockIdx.x] = (float)s;
    }
}

__global__ void vq_finalize(float* __restrict__ out_loss) {
    __shared__ double s[256];
    int tid = threadIdx.x;
    s[tid] = (tid < GRID) ? (double)g_part[tid] : 0.0;
    __syncthreads();
    for (int o = 128; o > 0; o >>= 1) {
        if (tid < o) s[tid] += s[tid + o];
        __syncthreads();
    }
    if (tid == 0)
        out_loss[0] = (float)(s[0] * (1.25 / 8388608.0));
}

extern "C" void kernel_launch(void* const* d_in, const int* in_sizes, int n_in,
                              void* d_out, int out_size) {
    const float* in = (const float*)d_in[0];
    const float* w  = (const float*)d_in[1];
    float* out      = (float*)d_out;

    float* out_idx  = out;
    float* out_q    = out + NTOK;
    float* out_loss = out + NTOK + NTOK * DIM;

    int smem = (DIM * KCODES + KCODES + 4) * (int)sizeof(float);
    cudaFuncSetAttribute(vq_main, cudaFuncAttributeMaxDynamicSharedMemorySize, smem);
    vq_main<<<GRID, THREADS, smem>>>(in, w, out_idx, out_q);
    vq_finalize<<<1, 256>>>(out_loss);
}

// round 7
// speedup vs baseline: 1.5067x; 1.2765x over previous
#include <cuda_runtime.h>
#include <cuda_bf16.h>
#include <float.h>

// VectorQuantizer: N=131072 tokens (32 x 64 x 64 NCHW), D=64, K=512.
// Outputs packed fp32: [indices 131072][quantized_st NCHW 8388608][loss 1].
//
// Bit-exact numerics (rel_err 0.0 since R3):
//   xsq  sequential rounded-mul/rounded-add; dot sequential FMA acc=0;
//   dist = fadd(fadd(xsq,-2*dot), wsq)  ==  add2(fma2(dot,-2,xsq), wsq);
//   strict-< ascending-k argmin; quantized_st = fadd(x, fsub(q,x)).
//
// R5: 2 tokens/thread share weight LDS (halves LDS+issue per FMA); balanced
// split 444 supertiles x 256 (444 = 3*148) + 136 tiles x 128 -> 896/SM max
// vs 886 floor. Packed f32x2 distance tail. Dummy launches shift ncu -s 5
// onto vq_main.

#define NTOK      131072
#define DIM       64
#define KCODES    512
#define HW        4096
#define THREADS   128
#define GRID      148
#define NSUPER    444        // supertiles of 256 tokens: 444*256 = 113664
#define PH2_BASE  113664
#define PH2_TILES 136        // 136*128 = 17408 remaining tokens

typedef unsigned long long u64;

__device__ float g_part[GRID];

__device__ __forceinline__ u64 fma2(u64 a, u64 b, u64 c) {
    u64 d;
    asm("fma.rn.f32x2 %0, %1, %2, %3;" : "=l"(d) : "l"(a), "l"(b), "l"(c));
    return d;
}
__device__ __forceinline__ u64 add2(u64 a, u64 b) {
    u64 d;
    asm("add.rn.f32x2 %0, %1, %2;" : "=l"(d) : "l"(a), "l"(b));
    return d;
}
__device__ __forceinline__ u64 pack2(float v) {
    u64 r;
    asm("mov.b64 %0, {%1, %1};" : "=l"(r) : "f"(v));
    return r;
}
__device__ __forceinline__ void unpack2(u64 p, float& lo, float& hi) {
    asm("mov.b64 {%0, %1}, %2;" : "=f"(lo), "=f"(hi) : "l"(p));
}

// Process NT tokens per thread (tokens t0, t0+tstride, ...), sharing the
// weight traffic across them. Bit-exact per-token numerics.
template <int NT>
__device__ __forceinline__ void process_tokens(
    const float* __restrict__ in, float* __restrict__ out_idx,
    float* __restrict__ out_q, const float* wt, const float* wsq,
    int t0, int tstride, float& loss_acc)
{
    int t[NT];
    const float* px[NT];
    float xv[NT][DIM];
    #pragma unroll
    for (int i = 0; i < NT; i++) {
        t[i]  = t0 + i * tstride;
        px[i] = in + ((t[i] >> 12) * (DIM * HW)) + (t[i] & (HW - 1));
        #pragma unroll
        for (int d = 0; d < DIM; d++) xv[i][d] = px[i][d * HW];
    }

    // ||x||^2: sequential scalar, rounded mul then rounded add (NO fma)
    u64 xsq2[NT];
    #pragma unroll
    for (int i = 0; i < NT; i++) {
        float s = 0.f;
        #pragma unroll
        for (int d = 0; d < DIM; d++)
            s = __fadd_rn(s, __fmul_rn(xv[i][d], xv[i][d]));
        xsq2[i] = pack2(s);
    }

    const u64 M2 = pack2(-2.0f);
    float best[NT];
    int bestk[NT];
    #pragma unroll
    for (int i = 0; i < NT; i++) { best[i] = FLT_MAX; bestk[i] = 0; }

    for (int kb = 0; kb < KCODES; kb += 16) {
        u64 acc[NT][8];
        #pragma unroll
        for (int i = 0; i < NT; i++)
            #pragma unroll
            for (int j = 0; j < 8; j++) acc[i][j] = 0ull;

        #pragma unroll
        for (int d = 0; d < DIM; d++) {
            u64 xp[NT];
            #pragma unroll
            for (int i = 0; i < NT; i++) xp[i] = pack2(xv[i][d]);
            const ulonglong2* row =
                reinterpret_cast<const ulonglong2*>(wt + d * KCODES + kb);
            #pragma unroll
            for (int q = 0; q < 4; q++) {
                ulonglong2 wp = row[q];            // LDS.128 broadcast
                #pragma unroll
                for (int i = 0; i < NT; i++) {
                    acc[i][2 * q]     = fma2(xp[i], wp.x, acc[i][2 * q]);
                    acc[i][2 * q + 1] = fma2(xp[i], wp.y, acc[i][2 * q + 1]);
                }
            }
        }

        #pragma unroll
        for (int j = 0; j < 8; j++) {
            u64 wpair = *reinterpret_cast<const u64*>(wsq + kb + 2 * j);
            #pragma unroll
            for (int i = 0; i < NT; i++) {
                // dist = (xsq - 2*dot) + wsq  (fma exact-product, then add)
                u64 dp = add2(fma2(acc[i][j], M2, xsq2[i]), wpair);
                float d0, d1;
                unpack2(dp, d0, d1);
                if (d0 < best[i]) { best[i] = d0; bestk[i] = kb + 2 * j; }
                if (d1 < best[i]) { best[i] = d1; bestk[i] = kb + 2 * j + 1; }
            }
        }
    }

    // Epilogue: straight-through output + loss partial.
    #pragma unroll
    for (int i = 0; i < NT; i++) {
        float* pq = out_q + ((t[i] >> 12) * (DIM * HW)) + (t[i] & (HW - 1));
        #pragma unroll
        for (int d = 0; d < DIM; d++) {
            float qv = wt[d * KCODES + bestk[i]];
            float e  = __fsub_rn(qv, xv[i][d]);    // q - x (one rounding)
            pq[d * HW] = __fadd_rn(xv[i][d], e);   // x + (q - x)
            loss_acc = fmaf(e, e, loss_acc);
        }
        out_idx[t[i]] = (float)bestk[i];
    }
}

__global__ void vq_nop() {}

__global__ __launch_bounds__(THREADS, 1) void vq_main(
    const float* __restrict__ in,   // [32, 64, 64, 64] NCHW
    const float* __restrict__ w,    // [512, 64]
    float* __restrict__ out_idx,    // [131072]
    float* __restrict__ out_q)      // [32, 64, 64, 64] NCHW
{
    extern __shared__ float sm[];
    float* wt  = sm;                 // [64][512] transposed weight
    float* wsq = sm + DIM * KCODES;  // [512]
    float* red = wsq + KCODES;       // [4]

    for (int e = threadIdx.x; e < KCODES * DIM; e += THREADS) {
        int k = e >> 6, d = e & 63;
        wt[d * KCODES + k] = w[e];
    }
    __syncthreads();

    for (int k = threadIdx.x; k < KCODES; k += THREADS) {
        float s = 0.f;
        for (int d = 0; d < DIM; d++) {
            float v = wt[d * KCODES + k];
            s = __fadd_rn(s, __fmul_rn(v, v));
        }
        wsq[k] = s;
    }
    __syncthreads();

    float loss_acc = 0.f;

    // Phase 1: 444 supertiles of 256 tokens, 2 tokens/thread (444 = 3*148).
    for (int st = blockIdx.x; st < NSUPER; st += GRID)
        process_tokens<2>(in, out_idx, out_q, wt, wsq,
                          st * 256 + threadIdx.x, 128, loss_acc);

    // Phase 2: 136 tiles of 128 tokens, 1 token/thread.
    for (int tile = blockIdx.x; tile < PH2_TILES; tile += GRID)
        process_tokens<1>(in, out_idx, out_q, wt, wsq,
                          PH2_BASE + tile * 128 + threadIdx.x, 0, loss_acc);

    // Deterministic per-CTA loss reduction
    #pragma unroll
    for (int o = 16; o > 0; o >>= 1)
        loss_acc += __shfl_xor_sync(0xffffffffu, loss_acc, o);
    int wid = threadIdx.x >> 5, lid = threadIdx.x & 31;
    if (lid == 0) red[wid] = loss_acc;
    __syncthreads();
    if (threadIdx.x == 0) {
        double s = 0.0;
        for (int i = 0; i < THREADS / 32; i++) s += (double)red[i];
        g_part[blockIdx.x] = (float)s;
    }
}

__global__ void vq_finalize(float* __restrict__ out_loss) {
    __shared__ double s[256];
    int tid = threadIdx.x;
    s[tid] = (tid < GRID) ? (double)g_part[tid] : 0.0;
    __syncthreads();
    for (int o = 128; o > 0; o >>= 1) {
        if (tid < o) s[tid] += s[tid + o];
        __syncthreads();
    }
    if (tid == 0)
        out_loss[0] = (float)(s[0] * (1.25 / 8388608.0));
}

extern "C" void kernel_launch(void* const* d_in, const int* in_sizes, int n_in,
                              void* d_out, int out_size) {
    const float* in = (const float*)d_in[0];
    const float* w  = (const float*)d_in[1];
    float* out      = (float*)d_out;

    float* out_idx  = out;
    float* out_q    = out + NTOK;
    float* out_loss = out + NTOK + NTOK * DIM;

    int smem = (DIM * KCODES + KCODES + 4) * (int)sizeof(float);
    cudaFuncSetAttribute(vq_main, cudaFuncAttributeMaxDynamicSharedMemorySize, smem);

    // Launch pattern period-4 (nop, main, finalize, nop): ncu -s 5 -c 1
    // captures the 6th launch == vq_main.
    vq_nop<<<1, 32>>>();
    vq_main<<<GRID, THREADS, smem>>>(in, w, out_idx, out_q);
    vq_finalize<<<1, 256>>>(out_loss);
    vq_nop<<<1, 32>>>();
}